// round 12
// baseline (speedup 1.0000x reference)
#include <cuda_runtime.h>
#include <cuda_bf16.h>
#include <math.h>

// -------- scratch (static device globals; no allocation anywhere) ----------
#define CAND_CAP   (1 << 20)
#define SMEM_KEYS  2048
#define NSAMP      256                 // sampler blocks (<< wave-1 residency)
__device__ float2 g_cand[CAND_CAP];    // .x = d2, .y = __int_as_float(index)
__device__ int    g_count;             // candidate count        (reset at end)
__device__ int    g_pub;               // samplers published     (reset at end)
__device__ int    g_done;              // blocks done            (reset at end)
__device__ int    g_flag;              // threshold-ready flag   (reset at end)
__device__ float  g_thresh;            // d2 threshold (<= true 16th-largest d2)
__device__ float  g_bmax[NSAMP];       // per-sampler chunk maxima

// ---------------------------------------------------------------------------
// ONE kernel: sample -> threshold -> filter -> exact top-16 -> epilogue.
//
// Threshold safety: thr = 16th largest of NSAMP maxima over DISJOINT 1024-pt
// chunks => at least 16 distinct points >= thr => thr <= global 16th-largest
// d^2, so no true top-16 point is filtered out.
//
// Deadlock safety: samplers (blocks 0..NSAMP-1) publish BEFORE spinning, and
// NSAMP=256 is far below guaranteed wave-1 residency, so the flag is always
// eventually set; later-wave blocks observe it immediately.
// ---------------------------------------------------------------------------
__global__ void k_locse(const float* __restrict__ P,
                        const float* __restrict__ W,    // (3,10) row-major
                        const float* __restrict__ bb,   // (3,)
                        const int*   __restrict__ ip,
                        float* __restrict__ out,        // (16,6)
                        int N, int nblocks, int nsamp)
{
    __shared__ float swarpf[8];
    __shared__ float sv[256];
    __shared__ float s_thr;
    __shared__ int   s_pred;                       // chooser / last flags
    __shared__ int   s_bits;                       // thr atomicMax accumulator
    __shared__ unsigned long long keys[SMEM_KEYS]; // 16 KB
    __shared__ unsigned long long swarp[8];
    __shared__ unsigned long long s_win;
    __shared__ int sel[16];

    const int t = threadIdx.x;
    const int b = blockIdx.x;
    const int p = b * 256 + t;
    const int j0 = 4 * p;

    const int i = *ip;
    const float px = P[6 * i + 0];
    const float py = P[6 * i + 1];
    const float pz = P[6 * i + 2];

    // ---- phase 1: load own points, compute d2 early (overlaps with spin) ----
    const bool full = (j0 + 3 < N);
    float d2a = -1.0f, d2b = -1.0f, d2c = -1.0f, d2d = -1.0f;
    if (full) {
        const float4* __restrict__ Pv = (const float4*)P;
        const float4 g0 = Pv[6 * p + 0];
        const float4 g1 = Pv[6 * p + 1];
        const float4 g2 = Pv[6 * p + 2];
        const float4 g3 = Pv[6 * p + 3];
        const float4 g4 = Pv[6 * p + 4];
        const float4 g5 = Pv[6 * p + 5];
        { const float dx = g0.x - px, dy = g0.y - py, dz = g0.z - pz; d2a = dx*dx + dy*dy + dz*dz; }
        { const float dx = g1.z - px, dy = g1.w - py, dz = g2.x - pz; d2b = dx*dx + dy*dy + dz*dz; }
        { const float dx = g3.x - px, dy = g3.y - py, dz = g3.z - pz; d2c = dx*dx + dy*dy + dz*dz; }
        { const float dx = g4.z - px, dy = g4.w - py, dz = g5.x - pz; d2d = dx*dx + dy*dy + dz*dz; }
    }

    // ---- phase 2: samplers publish chunk max; 256th publisher sets thr ----
    if (b < nsamp) {
        float m = fmaxf(fmaxf(d2a, d2b), fmaxf(d2c, d2d));
        #pragma unroll
        for (int s = 16; s > 0; s >>= 1)
            m = fmaxf(m, __shfl_xor_sync(0xffffffffu, m, s));
        if ((t & 31) == 0) swarpf[t >> 5] = m;
        __syncthreads();
        if (t == 0) {
            float mm = swarpf[0];
            #pragma unroll
            for (int w = 1; w < 8; w++) mm = fmaxf(mm, swarpf[w]);
            g_bmax[b] = mm;
            __threadfence();
            s_pred = (atomicAdd(&g_pub, 1) == nsamp - 1);
            s_bits = 0;
        }
        __syncthreads();
        if (s_pred) {
            // chooser block: rank-select 16th largest of nsamp maxima in smem
            sv[t] = (t < nsamp) ? g_bmax[t] : -1.0f;
            __syncthreads();
            const float my = sv[t];
            int g = 0;
            #pragma unroll 16
            for (int q = 0; q < 256; q++) g += (sv[q] > my) ? 1 : 0;
            if (g >= 15 && my >= 0.0f) atomicMax(&s_bits, __float_as_int(my));
            __syncthreads();
            if (t == 0) {
                g_thresh = __int_as_float(s_bits);
                __threadfence();
                atomicExch(&g_flag, 1);
            }
        }
    }

    // ---- phase 3: wait for threshold (thread 0 polls; loads already in flight)
    if (t == 0) {
        while (atomicAdd(&g_flag, 0) == 0) __nanosleep(64);
        __threadfence();
        s_thr = g_thresh;
    }
    __syncthreads();
    const float thr = s_thr;

    // ---- phase 4: append survivors ----
    if (full) {
        if (d2a >= thr) { const int pos = atomicAdd(&g_count, 1); if (pos < CAND_CAP) g_cand[pos] = make_float2(d2a, __int_as_float(j0 + 0)); }
        if (d2b >= thr) { const int pos = atomicAdd(&g_count, 1); if (pos < CAND_CAP) g_cand[pos] = make_float2(d2b, __int_as_float(j0 + 1)); }
        if (d2c >= thr) { const int pos = atomicAdd(&g_count, 1); if (pos < CAND_CAP) g_cand[pos] = make_float2(d2c, __int_as_float(j0 + 2)); }
        if (d2d >= thr) { const int pos = atomicAdd(&g_count, 1); if (pos < CAND_CAP) g_cand[pos] = make_float2(d2d, __int_as_float(j0 + 3)); }
    } else if (j0 < N) {
        for (int j = j0; j < N; j++) {
            const float dx = P[6 * j + 0] - px;
            const float dy = P[6 * j + 1] - py;
            const float dz = P[6 * j + 2] - pz;
            const float d2 = dx * dx + dy * dy + dz * dz;
            if (d2 >= thr) {
                const int pos = atomicAdd(&g_count, 1);
                if (pos < CAND_CAP) g_cand[pos] = make_float2(d2, __int_as_float(j));
            }
        }
    }

    // ---- phase 5: last block does exact top-16 + epilogue ----
    __threadfence();
    __syncthreads();
    if (t == 0) s_pred = (atomicAdd(&g_done, 1) == nblocks - 1);
    __syncthreads();
    if (!s_pred) return;

    __threadfence();                      // acquire all g_cand / g_count
    int cnt = g_count;
    if (cnt > SMEM_KEYS) cnt = SMEM_KEYS; // survivors ~500; 4x margin

    // packed key: (bits(sqrt(d2)) << 32) | ~idx  -> max == (d desc, idx asc),
    // matching jax.lax.top_k tie semantics.
    for (int q = t; q < cnt; q += 256) {
        const float2 cv = g_cand[q];
        const unsigned int db = __float_as_uint(sqrtf(cv.x));
        const unsigned int ik = ~(unsigned int)__float_as_int(cv.y);
        keys[q] = ((unsigned long long)db << 32) | ik;
    }
    __syncthreads();

    for (int r = 0; r < 16; r++) {
        unsigned long long mk = 0; int mpos = -1;
        for (int q = t; q < cnt; q += 256) {
            const unsigned long long k = keys[q];
            if (k > mk) { mk = k; mpos = q; }
        }
        unsigned long long wk = mk;
        #pragma unroll
        for (int s = 16; s > 0; s >>= 1) {
            const unsigned long long o = __shfl_xor_sync(0xffffffffu, wk, s);
            if (o > wk) wk = o;
        }
        if ((t & 31) == 0) swarp[t >> 5] = wk;
        __syncthreads();
        if (t < 8) {
            unsigned long long v = swarp[t];
            #pragma unroll
            for (int s = 4; s > 0; s >>= 1) {
                const unsigned long long o = __shfl_xor_sync(0xffu, v, s);
                if (o > v) v = o;
            }
            if (t == 0) s_win = v;
        }
        __syncthreads();
        const unsigned long long win = s_win;
        if (mk == win && mpos >= 0) keys[mpos] = 0ULL;  // unique owner removes
        if (t == 0) sel[r] = (int)(~(unsigned int)(win & 0xFFFFFFFFULL));
        __syncthreads();
    }

    if (t < 16) {
        const int idx = sel[t];
        const float nx = P[6 * idx + 0];
        const float ny = P[6 * idx + 1];
        const float nz = P[6 * idx + 2];
        const float dx = px - nx, dy = py - ny, dz = pz - nz;
        const float dist = sqrtf(dx * dx + dy * dy + dz * dz);

        float feat[10] = {px, py, pz, nx, ny, nz, dx, dy, dz, dist};

        out[6 * t + 0] = nx;
        out[6 * t + 1] = ny;
        out[6 * t + 2] = nz;
        #pragma unroll
        for (int c = 0; c < 3; c++) {
            float acc = bb[c];
            #pragma unroll
            for (int j = 0; j < 10; j++)
                acc += feat[j] * W[c * 10 + j];
            out[6 * t + 3 + c] = acc;
        }
    }

    // ---- reset globals so every graph replay starts from a clean state ----
    if (t == 0) {
        g_count = 0;
        g_pub = 0;
        g_done = 0;
        atomicExch(&g_flag, 0);
    }
}

// ---------------------------------------------------------------------------
extern "C" void kernel_launch(void* const* d_in, const int* in_sizes, int n_in,
                              void* d_out, int out_size)
{
    const float* P  = (const float*)d_in[0];
    const float* W  = (const float*)d_in[1];
    const float* b  = (const float*)d_in[2];
    const int*   ip = (const int*)d_in[3];
    float* out = (float*)d_out;

    const int N = in_sizes[0] / 6;

    const int nblocks = (N + 1023) / 1024;          // 4 pts/thread, 256 thr
    int nsamp = NSAMP;
    const int fullblocks = N / 1024;
    if (nsamp > fullblocks) nsamp = (fullblocks > 0) ? fullblocks : 1;

    k_locse<<<nblocks, 256>>>(P, W, b, ip, out, N, nblocks, nsamp);
}

// round 13
// speedup vs baseline: 1.1339x; 1.1339x over previous
#include <cuda_runtime.h>
#include <cuda_bf16.h>
#include <math.h>

// -------- scratch (static device globals; no allocation anywhere) ----------
#define CAND_CAP   (1 << 20)
#define SMEM_KEYS  2048
#define NSAMP      256                 // sampler blocks
#define NBLOCKS    592                 // 148 SMs x 4 blocks -> exactly 1 wave
#define NTHREADS   256
__device__ float2 g_cand[CAND_CAP];    // .x = d2, .y = __int_as_float(index)
__device__ int    g_count;             // candidate count        (reset at end)
__device__ int    g_pub;               // samplers published     (reset at end)
__device__ int    g_done;              // blocks done            (reset at end)
__device__ int    g_flag;              // threshold-ready flag   (reset at end)
__device__ float  g_thresh;            // d2 threshold (<= true 16th-largest d2)
__device__ float  g_bmax[NSAMP];       // per-sampler chunk maxima

// ---------------------------------------------------------------------------
// ONE persistent kernel, single wave (592 blocks on 148 SMs):
//   sample -> threshold -> grid-stride filter -> exact top-16 -> epilogue.
//
// Threshold safety: thr = 16th largest of nsamp maxima over DISJOINT 1024-pt
// chunks => >= 16 distinct points >= thr => thr <= global 16th-largest d^2.
//
// Deadlock safety: every block is resident (1 wave); samplers publish before
// anyone spins, so g_flag is always set.
// ---------------------------------------------------------------------------
__global__ void __launch_bounds__(NTHREADS, 4)
k_locse(const float* __restrict__ P,
        const float* __restrict__ W,    // (3,10) row-major
        const float* __restrict__ bb,   // (3,)
        const int*   __restrict__ ip,
        float* __restrict__ out,        // (16,6)
        int N, int nblocks, int nsamp)
{
    __shared__ float swarpf[8];
    __shared__ float sv[256];
    __shared__ float s_thr;
    __shared__ int   s_pred;
    __shared__ int   s_bits;
    __shared__ unsigned long long keys[SMEM_KEYS]; // 16 KB
    __shared__ unsigned long long swarp[8];
    __shared__ unsigned long long s_win;
    __shared__ int sel[16];

    const int t = threadIdx.x;
    const int b = blockIdx.x;
    const int ngroups = N >> 2;                    // groups of 4 points
    const int gstride = nblocks * NTHREADS;

    const int i = *ip;
    const float px = P[6 * i + 0];
    const float py = P[6 * i + 1];
    const float pz = P[6 * i + 2];

    const float4* __restrict__ Pv = (const float4*)P;

    // ---- phase 1: first group (g0 = b*256 + t), d2 kept in registers ----
    const int grp0 = b * NTHREADS + t;
    float d2a = -1.0f, d2b = -1.0f, d2c = -1.0f, d2d = -1.0f;
    const int j00 = 4 * grp0;
    if (grp0 < ngroups) {
        const float4 f0 = Pv[6 * grp0 + 0];
        const float4 f1 = Pv[6 * grp0 + 1];
        const float4 f2 = Pv[6 * grp0 + 2];
        const float4 f3 = Pv[6 * grp0 + 3];
        const float4 f4 = Pv[6 * grp0 + 4];
        const float4 f5 = Pv[6 * grp0 + 5];
        { const float dx = f0.x - px, dy = f0.y - py, dz = f0.z - pz; d2a = dx*dx + dy*dy + dz*dz; }
        { const float dx = f1.z - px, dy = f1.w - py, dz = f2.x - pz; d2b = dx*dx + dy*dy + dz*dz; }
        { const float dx = f3.x - px, dy = f3.y - py, dz = f3.z - pz; d2c = dx*dx + dy*dy + dz*dz; }
        { const float dx = f4.z - px, dy = f4.w - py, dz = f5.x - pz; d2d = dx*dx + dy*dy + dz*dz; }
    }

    // ---- phase 2: samplers publish first-chunk max; last one sets thr ----
    if (b < nsamp) {
        float m = fmaxf(fmaxf(d2a, d2b), fmaxf(d2c, d2d));
        #pragma unroll
        for (int s = 16; s > 0; s >>= 1)
            m = fmaxf(m, __shfl_xor_sync(0xffffffffu, m, s));
        if ((t & 31) == 0) swarpf[t >> 5] = m;
        __syncthreads();
        if (t == 0) {
            float mm = swarpf[0];
            #pragma unroll
            for (int w = 1; w < 8; w++) mm = fmaxf(mm, swarpf[w]);
            g_bmax[b] = mm;
            __threadfence();
            s_pred = (atomicAdd(&g_pub, 1) == nsamp - 1);
            s_bits = 0;
        }
        __syncthreads();
        if (s_pred) {
            sv[t] = (t < nsamp) ? g_bmax[t] : -1.0f;
            __syncthreads();
            const float my = sv[t];
            int g = 0;
            #pragma unroll 16
            for (int q = 0; q < 256; q++) g += (sv[q] > my) ? 1 : 0;
            if (g >= 15 && my >= 0.0f) atomicMax(&s_bits, __float_as_int(my));
            __syncthreads();
            if (t == 0) {
                g_thresh = __int_as_float(s_bits);
                __threadfence();
                atomicExch(&g_flag, 1);
            }
        }
    }

    // ---- phase 3: wait for threshold ----
    if (t == 0) {
        while (atomicAdd(&g_flag, 0) == 0) __nanosleep(64);
        __threadfence();
        s_thr = g_thresh;
    }
    __syncthreads();
    const float thr = s_thr;

    // ---- phase 4a: append survivors of the first (already-loaded) group ----
    if (grp0 < ngroups) {
        if (d2a >= thr) { const int pos = atomicAdd(&g_count, 1); if (pos < CAND_CAP) g_cand[pos] = make_float2(d2a, __int_as_float(j00 + 0)); }
        if (d2b >= thr) { const int pos = atomicAdd(&g_count, 1); if (pos < CAND_CAP) g_cand[pos] = make_float2(d2b, __int_as_float(j00 + 1)); }
        if (d2c >= thr) { const int pos = atomicAdd(&g_count, 1); if (pos < CAND_CAP) g_cand[pos] = make_float2(d2c, __int_as_float(j00 + 2)); }
        if (d2d >= thr) { const int pos = atomicAdd(&g_count, 1); if (pos < CAND_CAP) g_cand[pos] = make_float2(d2d, __int_as_float(j00 + 3)); }
    }

    // ---- phase 4b: grid-stride over remaining groups ----
    for (int grp = grp0 + gstride; grp < ngroups; grp += gstride) {
        const float4 f0 = Pv[6 * grp + 0];
        const float4 f1 = Pv[6 * grp + 1];
        const float4 f2 = Pv[6 * grp + 2];
        const float4 f3 = Pv[6 * grp + 3];
        const float4 f4 = Pv[6 * grp + 4];
        const float4 f5 = Pv[6 * grp + 5];
        float e2a, e2b, e2c, e2d;
        { const float dx = f0.x - px, dy = f0.y - py, dz = f0.z - pz; e2a = dx*dx + dy*dy + dz*dz; }
        { const float dx = f1.z - px, dy = f1.w - py, dz = f2.x - pz; e2b = dx*dx + dy*dy + dz*dz; }
        { const float dx = f3.x - px, dy = f3.y - py, dz = f3.z - pz; e2c = dx*dx + dy*dy + dz*dz; }
        { const float dx = f4.z - px, dy = f4.w - py, dz = f5.x - pz; e2d = dx*dx + dy*dy + dz*dz; }
        const int j0 = 4 * grp;
        if (e2a >= thr) { const int pos = atomicAdd(&g_count, 1); if (pos < CAND_CAP) g_cand[pos] = make_float2(e2a, __int_as_float(j0 + 0)); }
        if (e2b >= thr) { const int pos = atomicAdd(&g_count, 1); if (pos < CAND_CAP) g_cand[pos] = make_float2(e2b, __int_as_float(j0 + 1)); }
        if (e2c >= thr) { const int pos = atomicAdd(&g_count, 1); if (pos < CAND_CAP) g_cand[pos] = make_float2(e2c, __int_as_float(j0 + 2)); }
        if (e2d >= thr) { const int pos = atomicAdd(&g_count, 1); if (pos < CAND_CAP) g_cand[pos] = make_float2(e2d, __int_as_float(j0 + 3)); }
    }

    // ---- phase 4c: scalar tail (N not divisible by 4) ----
    if (b == 0 && t < (N & 3)) {
        const int j = (ngroups << 2) + t;
        const float dx = P[6 * j + 0] - px;
        const float dy = P[6 * j + 1] - py;
        const float dz = P[6 * j + 2] - pz;
        const float d2 = dx * dx + dy * dy + dz * dz;
        if (d2 >= thr) {
            const int pos = atomicAdd(&g_count, 1);
            if (pos < CAND_CAP) g_cand[pos] = make_float2(d2, __int_as_float(j));
        }
    }

    // ---- phase 5: last block does exact top-16 + epilogue ----
    __threadfence();
    __syncthreads();
    if (t == 0) s_pred = (atomicAdd(&g_done, 1) == nblocks - 1);
    __syncthreads();
    if (!s_pred) return;

    __threadfence();                      // acquire all g_cand / g_count
    int cnt = g_count;
    if (cnt > SMEM_KEYS) cnt = SMEM_KEYS; // survivors ~500; 4x margin

    // packed key: (bits(sqrt(d2)) << 32) | ~idx -> max == (d desc, idx asc),
    // matching jax.lax.top_k tie semantics.
    for (int q = t; q < cnt; q += NTHREADS) {
        const float2 cv = g_cand[q];
        const unsigned int db = __float_as_uint(sqrtf(cv.x));
        const unsigned int ik = ~(unsigned int)__float_as_int(cv.y);
        keys[q] = ((unsigned long long)db << 32) | ik;
    }
    __syncthreads();

    for (int r = 0; r < 16; r++) {
        unsigned long long mk = 0; int mpos = -1;
        for (int q = t; q < cnt; q += NTHREADS) {
            const unsigned long long k = keys[q];
            if (k > mk) { mk = k; mpos = q; }
        }
        unsigned long long wk = mk;
        #pragma unroll
        for (int s = 16; s > 0; s >>= 1) {
            const unsigned long long o = __shfl_xor_sync(0xffffffffu, wk, s);
            if (o > wk) wk = o;
        }
        if ((t & 31) == 0) swarp[t >> 5] = wk;
        __syncthreads();
        if (t < 8) {
            unsigned long long v = swarp[t];
            #pragma unroll
            for (int s = 4; s > 0; s >>= 1) {
                const unsigned long long o = __shfl_xor_sync(0xffu, v, s);
                if (o > v) v = o;
            }
            if (t == 0) s_win = v;
        }
        __syncthreads();
        const unsigned long long win = s_win;
        if (mk == win && mpos >= 0) keys[mpos] = 0ULL;  // unique owner removes
        if (t == 0) sel[r] = (int)(~(unsigned int)(win & 0xFFFFFFFFULL));
        __syncthreads();
    }

    if (t < 16) {
        const int idx = sel[t];
        const float nx = P[6 * idx + 0];
        const float ny = P[6 * idx + 1];
        const float nz = P[6 * idx + 2];
        const float dx = px - nx, dy = py - ny, dz = pz - nz;
        const float dist = sqrtf(dx * dx + dy * dy + dz * dz);

        float feat[10] = {px, py, pz, nx, ny, nz, dx, dy, dz, dist};

        out[6 * t + 0] = nx;
        out[6 * t + 1] = ny;
        out[6 * t + 2] = nz;
        #pragma unroll
        for (int c = 0; c < 3; c++) {
            float acc = bb[c];
            #pragma unroll
            for (int j = 0; j < 10; j++)
                acc += feat[j] * W[c * 10 + j];
            out[6 * t + 3 + c] = acc;
        }
    }

    // ---- reset globals so every graph replay starts clean ----
    if (t == 0) {
        g_count = 0;
        g_pub = 0;
        g_done = 0;
        atomicExch(&g_flag, 0);
    }
}

// ---------------------------------------------------------------------------
extern "C" void kernel_launch(void* const* d_in, const int* in_sizes, int n_in,
                              void* d_out, int out_size)
{
    const float* P  = (const float*)d_in[0];
    const float* W  = (const float*)d_in[1];
    const float* b  = (const float*)d_in[2];
    const int*   ip = (const int*)d_in[3];
    float* out = (float*)d_out;

    const int N = in_sizes[0] / 6;

    const int ngroups = N / 4;
    int nblocks = NBLOCKS;
    const int maxblocks = (ngroups + NTHREADS - 1) / NTHREADS;
    if (nblocks > maxblocks) nblocks = (maxblocks > 0) ? maxblocks : 1;

    // samplers need their full first chunk in range: block b's groups are
    // [b*256, b*256+256) -> need (nsamp*256)*4 <= N
    int nsamp = NSAMP;
    const int fullchunks = N / (NTHREADS * 4);
    if (nsamp > fullchunks) nsamp = (fullchunks > 0) ? fullchunks : 1;
    if (nsamp > nblocks) nsamp = nblocks;

    k_locse<<<nblocks, NTHREADS>>>(P, W, b, ip, out, N, nblocks, nsamp);
}